// round 10
// baseline (speedup 1.0000x reference)
#include <cuda_runtime.h>
#include <cuda_bf16.h>
#include <math.h>
#include <stdint.h>

#define BATCH 128
#define NPTS  1024
#define DIM   128
#define UMAX  0xFFFFFFFFu

// Scratch (device globals: allocation-free).
// g_D holds PACKED keys: high 22 bits = round-to-nearest of dist^2 float bits,
// low 10 bits = column index. Monotone in dist^2; ties -> lower index (matches
// jnp.argmin). 22-bit rounding validated: ~0.5 frontier candidates per
// quantization bin -> selection bias ~1e-5 (16-bit keys would give ~30/bin and
// ~1e-3 bias -- rejected).
__device__ uint32_t       g_D[(size_t)BATCH * NPTS * NPTS];   // 512 MB
__device__ __nv_bfloat16  g_Xb[(size_t)BATCH * NPTS * DIM];   // 32 MB
__device__ float          g_norm[BATCH * NPTS];
__device__ float          g_partial[BATCH];

// ---------------------------------------------------------------------------
// Kernel 1: fused row norms (fp32 exact) + bf16 conversion. One warp per point.
// ---------------------------------------------------------------------------
__global__ void prep_kernel(const float* __restrict__ X) {
    int warp = (blockIdx.x * blockDim.x + threadIdx.x) >> 5;
    int lane = threadIdx.x & 31;
    if (warp >= BATCH * NPTS) return;
    const float4* row = (const float4*)(X + (size_t)warp * DIM);
    float4 v = row[lane];
    __nv_bfloat162* dst = (__nv_bfloat162*)(g_Xb + (size_t)warp * DIM) + lane * 2;
    dst[0] = __floats2bfloat162_rn(v.x, v.y);
    dst[1] = __floats2bfloat162_rn(v.z, v.w);
    float s = v.x * v.x + v.y * v.y + v.z * v.z + v.w * v.w;
    #pragma unroll
    for (int o = 16; o; o >>= 1) s += __shfl_down_sync(0xffffffffu, s, o);
    if (lane == 0) g_norm[warp] = s;
}

// ---------------------------------------------------------------------------
// Kernel 2: batched Gram via bf16 mma.sync; epilogue packs dist^2 keys.
// (smem-LDS-throughput bound; unchanged this round.)
// ---------------------------------------------------------------------------
#define KCH   64
#define LDR   72   // padded smem row length in bf16 (conflict-free)

__device__ __forceinline__ void mma16816(float* c, const uint32_t* a,
                                         uint32_t b0, uint32_t b1) {
    asm volatile(
        "mma.sync.aligned.m16n8k16.row.col.f32.bf16.bf16.f32 "
        "{%0,%1,%2,%3}, {%4,%5,%6,%7}, {%8,%9}, {%0,%1,%2,%3};\n"
        : "+f"(c[0]), "+f"(c[1]), "+f"(c[2]), "+f"(c[3])
        : "r"(a[0]), "r"(a[1]), "r"(a[2]), "r"(a[3]), "r"(b0), "r"(b1));
}

__device__ __forceinline__ uint32_t pack_key(float d2, int col) {
    return ((__float_as_uint(d2) + 0x200u) & 0xFFFFFC00u) | (uint32_t)col;
}

__global__ __launch_bounds__(256, 2)
void dist_kernel() {
    __shared__ __align__(16) __nv_bfloat16 As[128 * LDR];
    __shared__ __align__(16) __nv_bfloat16 Bs[128 * LDR];

    const int b  = blockIdx.z;
    const int I  = blockIdx.y * 128;
    const int J  = blockIdx.x * 128;
    const int tid  = threadIdx.x;
    const int lane = tid & 31;
    const int wid  = tid >> 5;
    const int wm   = wid & 3;
    const int wn   = wid >> 2;

    const __nv_bfloat16* Xb = g_Xb + (size_t)b * NPTS * DIM;

    float acc[2][8][4];
    #pragma unroll
    for (int m = 0; m < 2; ++m)
        #pragma unroll
        for (int n = 0; n < 8; ++n)
            #pragma unroll
            for (int q = 0; q < 4; ++q) acc[m][n][q] = 0.f;

    const uint32_t* As32 = (const uint32_t*)As;
    const uint32_t* Bs32 = (const uint32_t*)Bs;

    for (int k0 = 0; k0 < DIM; k0 += KCH) {
        __syncthreads();
        #pragma unroll
        for (int i = 0; i < 4; ++i) {
            int e  = tid + 256 * i;
            int r  = e >> 3;
            int c8 = e & 7;
            uint4 va = *(const uint4*)(Xb + (size_t)(I + r) * DIM + k0 + c8 * 8);
            uint4 vb = *(const uint4*)(Xb + (size_t)(J + r) * DIM + k0 + c8 * 8);
            *(uint4*)(As + r * LDR + c8 * 8) = va;
            *(uint4*)(Bs + r * LDR + c8 * 8) = vb;
        }
        __syncthreads();

        #pragma unroll
        for (int ks = 0; ks < KCH / 16; ++ks) {
            const int c = ks * 16 + (lane & 3) * 2;
            uint32_t a[2][4];
            #pragma unroll
            for (int mt = 0; mt < 2; ++mt) {
                int r0 = wm * 32 + mt * 16 + (lane >> 2);
                a[mt][0] = As32[(r0 * LDR + c) >> 1];
                a[mt][1] = As32[((r0 + 8) * LDR + c) >> 1];
                a[mt][2] = As32[(r0 * LDR + c + 8) >> 1];
                a[mt][3] = As32[((r0 + 8) * LDR + c + 8) >> 1];
            }
            #pragma unroll
            for (int nt = 0; nt < 8; ++nt) {
                int jr = wn * 64 + nt * 8 + (lane >> 2);
                uint32_t b0 = Bs32[(jr * LDR + c) >> 1];
                uint32_t b1 = Bs32[(jr * LDR + c + 8) >> 1];
                mma16816(acc[0][nt], a[0], b0, b1);
                mma16816(acc[1][nt], a[1], b0, b1);
            }
        }
    }

    uint32_t* Db = g_D + ((size_t)b << 20);
    const float* nb = g_norm + b * NPTS;
    #pragma unroll
    for (int mt = 0; mt < 2; ++mt) {
        int r0 = I + wm * 32 + mt * 16 + (lane >> 2);
        float ni0 = nb[r0], ni1 = nb[r0 + 8];
        #pragma unroll
        for (int nt = 0; nt < 8; ++nt) {
            int col = J + wn * 64 + nt * 8 + (lane & 3) * 2;
            float nj0 = nb[col], nj1 = nb[col + 1];
            uint2 v0, v1;
            v0.x = pack_key(fmaxf(ni0 + nj0 - 2.f * acc[mt][nt][0], 0.f), col);
            v0.y = pack_key(fmaxf(ni0 + nj1 - 2.f * acc[mt][nt][1], 0.f), col + 1);
            v1.x = pack_key(fmaxf(ni1 + nj0 - 2.f * acc[mt][nt][2], 0.f), col);
            v1.y = pack_key(fmaxf(ni1 + nj1 - 2.f * acc[mt][nt][3], 0.f), col + 1);
            *(uint2*)(Db + (size_t)r0 * NPTS + col)       = v0;
            *(uint2*)(Db + (size_t)(r0 + 8) * NPTS + col) = v1;
        }
    }
}

// ---------------------------------------------------------------------------
// Kernel 3: Prim's MST. 256 threads/CTA, 4 consecutive points/thread.
// Single barrier/iter (parity-double-buffered per-warp pairs, all-thread
// combine). Sticky visited explicit (R3/R5 lesson).
//
// NEW: 4-entry register-resident ROW CACHE. g_D rows are immutable during
// prim, so a prefetched runner-up row never goes stale; losing runner-ups
// stay prime candidates for several iterations. Each iteration prefetches
// gsec's row into ring slot (it&3) (dup-suppressed); lookup of row j checks
// the 4 cached ids (uniform compares) before falling back to the ~600-cycle
// DRAM fetch. Cached bytes are bit-identical to memory -> numerics untouched.
// ---------------------------------------------------------------------------
__device__ __forceinline__ uint32_t upd(uint32_t m, uint32_t r, int idx, int j) {
    uint32_t nx = min(m, r);
    return (m == UMAX || idx == j) ? UMAX : nx;
}

__global__ __launch_bounds__(256, 1)
void prim_kernel() {
    const int b    = blockIdx.x;
    const int tid  = threadIdx.x;
    const int lane = tid & 31;
    const int wid  = tid >> 5;
    const int p0   = tid * 4;

    const uint32_t* Db = g_D + ((size_t)b << 20);

    // init: mind = row 0 keys; point 0 marked visited
    uint4 m = ((const uint4*)Db)[tid];
    if (tid == 0) m.x = UMAX;

    __shared__ __align__(16) uint2 s_warp[2][8];   // [parity][warp] (min, second)

    float total = 0.f;

    // 4-entry immutable row cache (ring). ids are block-uniform.
    uint4 C0, C1, C2, C3;
    int id0 = -1, id1 = -1, id2 = -1, id3 = -1;

    for (int it = 0; it < NPTS - 1; ++it) {
        const int par = it & 1;
        // ---- per-thread min of 4, then warp (min, second) via 2 REDUX ----
        uint32_t km = min(min(m.x, m.y), min(m.z, m.w));
        uint32_t wbest = __reduce_min_sync(0xffffffffu, km);
        uint32_t km2   = (km == wbest) ? UMAX : km;
        uint32_t wsec  = __reduce_min_sync(0xffffffffu, km2);
        if (lane == 0) s_warp[par][wid] = make_uint2(wbest, wsec);
        __syncthreads();   // the ONLY barrier this iteration

        // ---- every thread combines the 8 pairs locally (broadcast LDS) ----
        uint4 q0 = *(const uint4*)&s_warp[par][0];
        uint4 q1 = *(const uint4*)&s_warp[par][2];
        uint4 q2 = *(const uint4*)&s_warp[par][4];
        uint4 q3 = *(const uint4*)&s_warp[par][6];
        uint32_t gbest = min(min(min(q0.x, q0.z), min(q1.x, q1.z)),
                             min(min(q2.x, q2.z), min(q3.x, q3.z)));
        uint32_t c0 = (q0.x == gbest) ? q0.y : q0.x;
        uint32_t c1 = (q0.z == gbest) ? q0.w : q0.z;
        uint32_t c2 = (q1.x == gbest) ? q1.y : q1.x;
        uint32_t c3 = (q1.z == gbest) ? q1.w : q1.z;
        uint32_t c4 = (q2.x == gbest) ? q2.y : q2.x;
        uint32_t c5 = (q2.z == gbest) ? q2.w : q2.z;
        uint32_t c6 = (q3.x == gbest) ? q3.y : q3.x;
        uint32_t c7 = (q3.z == gbest) ? q3.w : q3.z;
        uint32_t gsec = min(min(min(c0, c1), min(c2, c3)),
                            min(min(c4, c5), min(c6, c7)));

        int j = (int)(gbest & 1023u);
        if (tid == 0) total += sqrtf(__uint_as_float(gbest & 0xFFFFFC00u));

        // ---- row j: cache lookup, then DRAM on miss (uniform branch) ----
        uint4 R;
        if      (j == id0) R = C0;
        else if (j == id1) R = C1;
        else if (j == id2) R = C2;
        else if (j == id3) R = C3;
        else R = ((const uint4*)(Db + ((size_t)j << 10)))[tid];

        // ---- prefetch gsec's row into the ring (dup-suppressed) ----
        int sj = (int)(gsec & 1023u);
        bool ins = (gsec != UMAX) &&
                   sj != id0 && sj != id1 && sj != id2 && sj != id3;
        if (ins) {
            uint4 P = ((const uint4*)(Db + ((size_t)sj << 10)))[tid];
            switch (it & 3) {
                case 0: C0 = P; id0 = sj; break;
                case 1: C1 = P; id1 = sj; break;
                case 2: C2 = P; id2 = sj; break;
                default: C3 = P; id3 = sj; break;
            }
        }
        // consumed row j can never be selected again; if cached, retire its id
        if (j == id0) id0 = -1;
        if (j == id1) id1 = -1;
        if (j == id2) id2 = -1;
        if (j == id3) id3 = -1;

        // ---- sticky min-update with fused visited-marking ----
        m.x = upd(m.x, R.x, p0 + 0, j);
        m.y = upd(m.y, R.y, p0 + 1, j);
        m.z = upd(m.z, R.z, p0 + 2, j);
        m.w = upd(m.w, R.w, p0 + 3, j);
    }
    if (tid == 0) g_partial[b] = total;
}

// ---------------------------------------------------------------------------
// Kernel 4: final scalar.
// ---------------------------------------------------------------------------
__global__ void final_kernel(float* __restrict__ out) {
    const int t = threadIdx.x;           // 128 threads
    const int lane = t & 31, wid = t >> 5;
    __shared__ float s[4];
    float v = g_partial[t];
    #pragma unroll
    for (int o = 16; o; o >>= 1) v += __shfl_down_sync(0xffffffffu, v, o);
    if (lane == 0) s[wid] = v;
    __syncthreads();
    if (t == 0) out[0] = (s[0] + s[1] + s[2] + s[3]) / (1023.f * (float)BATCH * 2.f);
}

// ---------------------------------------------------------------------------
extern "C" void kernel_launch(void* const* d_in, const int* in_sizes, int n_in,
                              void* d_out, int out_size) {
    (void)in_sizes; (void)n_in; (void)out_size;
    const float* X = (const float*)d_in[0];
    float* out = (float*)d_out;

    prep_kernel<<<16384, 256>>>(X);            // fused norms + bf16 convert
    dist_kernel<<<dim3(8, 8, BATCH), 256>>>();
    prim_kernel<<<BATCH, 256>>>();
    final_kernel<<<1, 128>>>(out);
}

// round 11
// speedup vs baseline: 1.2806x; 1.2806x over previous
#include <cuda_runtime.h>
#include <cuda_bf16.h>
#include <math.h>
#include <stdint.h>

#define BATCH 128
#define NPTS  1024
#define DIM   128
#define UMAX  0xFFFFFFFFu

// Scratch (device globals: allocation-free).
// g_D holds PACKED keys: high 22 bits = round-to-nearest of dist^2 float bits,
// low 10 bits = column index. Monotone in dist^2; ties -> lower index (matches
// jnp.argmin).
__device__ uint32_t       g_D[(size_t)BATCH * NPTS * NPTS];    // 512 MB
__device__ __nv_bfloat16  g_Xb[(size_t)BATCH * NPTS * DIM];    // 32 MB
__device__ float          g_norm[BATCH * NPTS];
__device__ float          g_partial[BATCH];
__device__ uint32_t       g_rowmin[(size_t)BATCH * NPTS * 16]; // per-row, per-64col-half argmin keys (8 MB)
__device__ uint4          g_nn[BATCH * NPTS];                  // static top-3 NN cols per point (2 MB)

__device__ __forceinline__ void prefetchL2(const void* p) {
    asm volatile("prefetch.global.L2 [%0];" :: "l"(p));
}

// ---------------------------------------------------------------------------
// Kernel 1: fused row norms (fp32 exact) + bf16 conversion. One warp per point.
// ---------------------------------------------------------------------------
__global__ void prep_kernel(const float* __restrict__ X) {
    int warp = (blockIdx.x * blockDim.x + threadIdx.x) >> 5;
    int lane = threadIdx.x & 31;
    if (warp >= BATCH * NPTS) return;
    const float4* row = (const float4*)(X + (size_t)warp * DIM);
    float4 v = row[lane];
    __nv_bfloat162* dst = (__nv_bfloat162*)(g_Xb + (size_t)warp * DIM) + lane * 2;
    dst[0] = __floats2bfloat162_rn(v.x, v.y);
    dst[1] = __floats2bfloat162_rn(v.z, v.w);
    float s = v.x * v.x + v.y * v.y + v.z * v.z + v.w * v.w;
    #pragma unroll
    for (int o = 16; o; o >>= 1) s += __shfl_down_sync(0xffffffffu, s, o);
    if (lane == 0) g_norm[warp] = s;
}

// ---------------------------------------------------------------------------
// Kernel 2: batched Gram via bf16 mma.sync; epilogue packs dist^2 keys AND
// emits per-(row, 64-col-half) argmin partials for the static NN table.
// ---------------------------------------------------------------------------
#define KCH   64
#define LDR   72   // padded smem row length in bf16 (conflict-free)

__device__ __forceinline__ void mma16816(float* c, const uint32_t* a,
                                         uint32_t b0, uint32_t b1) {
    asm volatile(
        "mma.sync.aligned.m16n8k16.row.col.f32.bf16.bf16.f32 "
        "{%0,%1,%2,%3}, {%4,%5,%6,%7}, {%8,%9}, {%0,%1,%2,%3};\n"
        : "+f"(c[0]), "+f"(c[1]), "+f"(c[2]), "+f"(c[3])
        : "r"(a[0]), "r"(a[1]), "r"(a[2]), "r"(a[3]), "r"(b0), "r"(b1));
}

__device__ __forceinline__ uint32_t pack_key(float d2, int col) {
    return ((__float_as_uint(d2) + 0x200u) & 0xFFFFFC00u) | (uint32_t)col;
}

__global__ __launch_bounds__(256, 2)
void dist_kernel() {
    __shared__ __align__(16) __nv_bfloat16 As[128 * LDR];
    __shared__ __align__(16) __nv_bfloat16 Bs[128 * LDR];

    const int b  = blockIdx.z;
    const int I  = blockIdx.y * 128;
    const int J  = blockIdx.x * 128;
    const int tid  = threadIdx.x;
    const int lane = tid & 31;
    const int wid  = tid >> 5;
    const int wm   = wid & 3;
    const int wn   = wid >> 2;

    const __nv_bfloat16* Xb = g_Xb + (size_t)b * NPTS * DIM;

    float acc[2][8][4];
    #pragma unroll
    for (int m = 0; m < 2; ++m)
        #pragma unroll
        for (int n = 0; n < 8; ++n)
            #pragma unroll
            for (int q = 0; q < 4; ++q) acc[m][n][q] = 0.f;

    const uint32_t* As32 = (const uint32_t*)As;
    const uint32_t* Bs32 = (const uint32_t*)Bs;

    for (int k0 = 0; k0 < DIM; k0 += KCH) {
        __syncthreads();
        #pragma unroll
        for (int i = 0; i < 4; ++i) {
            int e  = tid + 256 * i;
            int r  = e >> 3;
            int c8 = e & 7;
            uint4 va = *(const uint4*)(Xb + (size_t)(I + r) * DIM + k0 + c8 * 8);
            uint4 vb = *(const uint4*)(Xb + (size_t)(J + r) * DIM + k0 + c8 * 8);
            *(uint4*)(As + r * LDR + c8 * 8) = va;
            *(uint4*)(Bs + r * LDR + c8 * 8) = vb;
        }
        __syncthreads();

        #pragma unroll
        for (int ks = 0; ks < KCH / 16; ++ks) {
            const int c = ks * 16 + (lane & 3) * 2;
            uint32_t a[2][4];
            #pragma unroll
            for (int mt = 0; mt < 2; ++mt) {
                int r0 = wm * 32 + mt * 16 + (lane >> 2);
                a[mt][0] = As32[(r0 * LDR + c) >> 1];
                a[mt][1] = As32[((r0 + 8) * LDR + c) >> 1];
                a[mt][2] = As32[(r0 * LDR + c + 8) >> 1];
                a[mt][3] = As32[((r0 + 8) * LDR + c + 8) >> 1];
            }
            #pragma unroll
            for (int nt = 0; nt < 8; ++nt) {
                int jr = wn * 64 + nt * 8 + (lane >> 2);
                uint32_t b0 = Bs32[(jr * LDR + c) >> 1];
                uint32_t b1 = Bs32[(jr * LDR + c + 8) >> 1];
                mma16816(acc[0][nt], a[0], b0, b1);
                mma16816(acc[1][nt], a[1], b0, b1);
            }
        }
    }

    uint32_t* Db = g_D + ((size_t)b << 20);
    const float* nb = g_norm + b * NPTS;
    #pragma unroll
    for (int mt = 0; mt < 2; ++mt) {
        int r0 = I + wm * 32 + mt * 16 + (lane >> 2);
        int r1 = r0 + 8;
        float ni0 = nb[r0], ni1 = nb[r1];
        uint32_t rm0 = UMAX, rm1 = UMAX;   // per-64col-half argmins (diag excl)
        #pragma unroll
        for (int nt = 0; nt < 8; ++nt) {
            int col = J + wn * 64 + nt * 8 + (lane & 3) * 2;
            float nj0 = nb[col], nj1 = nb[col + 1];
            uint2 v0, v1;
            v0.x = pack_key(fmaxf(ni0 + nj0 - 2.f * acc[mt][nt][0], 0.f), col);
            v0.y = pack_key(fmaxf(ni0 + nj1 - 2.f * acc[mt][nt][1], 0.f), col + 1);
            v1.x = pack_key(fmaxf(ni1 + nj0 - 2.f * acc[mt][nt][2], 0.f), col);
            v1.y = pack_key(fmaxf(ni1 + nj1 - 2.f * acc[mt][nt][3], 0.f), col + 1);
            *(uint2*)(Db + (size_t)r0 * NPTS + col) = v0;
            *(uint2*)(Db + (size_t)r1 * NPTS + col) = v1;
            rm0 = min(rm0, min((col == r0) ? UMAX : v0.x, (col + 1 == r0) ? UMAX : v0.y));
            rm1 = min(rm1, min((col == r1) ? UMAX : v1.x, (col + 1 == r1) ? UMAX : v1.y));
        }
        // combine across the 4 lanes sharing these rows (lane&3 varies)
        rm0 = min(rm0, __shfl_xor_sync(0xffffffffu, rm0, 1));
        rm0 = min(rm0, __shfl_xor_sync(0xffffffffu, rm0, 2));
        rm1 = min(rm1, __shfl_xor_sync(0xffffffffu, rm1, 1));
        rm1 = min(rm1, __shfl_xor_sync(0xffffffffu, rm1, 2));
        if ((lane & 3) == 0) {
            int half = blockIdx.x * 2 + wn;   // 0..15
            g_rowmin[(((size_t)b * NPTS + r0) << 4) + half] = rm0;
            g_rowmin[(((size_t)b * NPTS + r1) << 4) + half] = rm1;
        }
    }
}

// ---------------------------------------------------------------------------
// Kernel 2b: reduce 16 per-half argmins -> static top-3 NN cols per point.
// ---------------------------------------------------------------------------
__global__ void nn_kernel() {
    int gid = blockIdx.x * 256 + threadIdx.x;    // 0 .. BATCH*NPTS-1
    const uint4* rm4 = (const uint4*)(g_rowmin + ((size_t)gid << 4));
    uint32_t b1 = UMAX, b2 = UMAX, b3 = UMAX;
    #pragma unroll
    for (int q = 0; q < 4; ++q) {
        uint4 v = rm4[q];
        uint32_t t[4] = {v.x, v.y, v.z, v.w};
        #pragma unroll
        for (int e = 0; e < 4; ++e) {
            uint32_t x = t[e];
            if (x < b1)      { b3 = b2; b2 = b1; b1 = x; }
            else if (x < b2) { b3 = b2; b2 = x; }
            else if (x < b3) { b3 = x; }
        }
    }
    g_nn[gid] = make_uint4(b1 & 1023u, b2 & 1023u, b3 & 1023u, 0u);
}

// ---------------------------------------------------------------------------
// Kernel 3: Prim's MST. 256 threads/CTA, 4 consecutive points/thread.
// Single barrier/iter; sticky visited explicit (R3/R5 lesson).
//
// Next-winner dichotomy: after adding j, the next selected vertex is either
// (a) the current runner-up gsec, or (b) argmin_unvisited d(j,.) — i.e. one
// of j's STATIC nearest neighbors. So: dual register speculation (gsec row +
// nn0[j] row) and L2 warming of nn1[j]/nn2[j] rows. All prefetched bytes are
// bit-identical to memory; selection logic and numerics untouched.
// ---------------------------------------------------------------------------
__device__ __forceinline__ uint32_t upd(uint32_t m, uint32_t r, int idx, int j) {
    uint32_t nx = min(m, r);
    return (m == UMAX || idx == j) ? UMAX : nx;
}

__global__ __launch_bounds__(256, 1)
void prim_kernel() {
    const int b    = blockIdx.x;
    const int tid  = threadIdx.x;
    const int lane = tid & 31;
    const int wid  = tid >> 5;
    const int p0   = tid * 4;

    const uint32_t* Db = g_D + ((size_t)b << 20);

    __shared__ __align__(16) uint2 s_warp[2][8];
    __shared__ __align__(16) uint4 s_nn[NPTS];       // 16 KB static NN table

    // stage NN table + init mind
    #pragma unroll
    for (int q = 0; q < 4; ++q)
        s_nn[tid + 256 * q] = g_nn[b * NPTS + tid + 256 * q];
    uint4 m = ((const uint4*)Db)[tid];
    if (tid == 0) m.x = UMAX;          // point 0 visited
    __syncthreads();

    float total = 0.f;
    int idA = -1, idB = -1;
    uint4 SA, SB;

    for (int it = 0; it < NPTS - 1; ++it) {
        const int par = it & 1;
        // ---- per-thread min of 4, then warp (min, second) via 2 REDUX ----
        uint32_t km = min(min(m.x, m.y), min(m.z, m.w));
        uint32_t wbest = __reduce_min_sync(0xffffffffu, km);
        uint32_t km2   = (km == wbest) ? UMAX : km;
        uint32_t wsec  = __reduce_min_sync(0xffffffffu, km2);
        if (lane == 0) s_warp[par][wid] = make_uint2(wbest, wsec);
        __syncthreads();   // the only barrier

        // ---- all-thread combine of the 8 (min, second) pairs ----
        uint4 q0 = *(const uint4*)&s_warp[par][0];
        uint4 q1 = *(const uint4*)&s_warp[par][2];
        uint4 q2 = *(const uint4*)&s_warp[par][4];
        uint4 q3 = *(const uint4*)&s_warp[par][6];
        uint32_t gbest = min(min(min(q0.x, q0.z), min(q1.x, q1.z)),
                             min(min(q2.x, q2.z), min(q3.x, q3.z)));
        uint32_t c0 = (q0.x == gbest) ? q0.y : q0.x;
        uint32_t c1 = (q0.z == gbest) ? q0.w : q0.z;
        uint32_t c2 = (q1.x == gbest) ? q1.y : q1.x;
        uint32_t c3 = (q1.z == gbest) ? q1.w : q1.z;
        uint32_t c4 = (q2.x == gbest) ? q2.y : q2.x;
        uint32_t c5 = (q2.z == gbest) ? q2.w : q2.z;
        uint32_t c6 = (q3.x == gbest) ? q3.y : q3.x;
        uint32_t c7 = (q3.z == gbest) ? q3.w : q3.z;
        uint32_t gsec = min(min(min(c0, c1), min(c2, c3)),
                            min(min(c4, c5), min(c6, c7)));

        int j = (int)(gbest & 1023u);
        if (tid == 0) total += sqrtf(__uint_as_float(gbest & 0xFFFFFC00u));

        // ---- row j: dual speculation check, DRAM on miss (uniform) ----
        uint4 R;
        if      (j == idA) R = SA;
        else if (j == idB) R = SB;
        else R = ((const uint4*)(Db + ((size_t)j << 10)))[tid];

        // ---- next-iteration prefetches ----
        uint4 nnj = s_nn[j];                         // broadcast LDS
        int sj = (int)(gsec & 1023u);
        int n0 = (int)nnj.x;
        if (n0 == sj) n0 = (int)nnj.y;
        SA = ((const uint4*)(Db + ((size_t)sj << 10)))[tid];
        SB = ((const uint4*)(Db + ((size_t)n0 << 10)))[tid];
        idA = (gsec == UMAX) ? -1 : sj;
        idB = n0;
        prefetchL2(Db + ((size_t)nnj.y << 10) + (tid << 2));
        prefetchL2(Db + ((size_t)nnj.z << 10) + (tid << 2));

        // ---- sticky min-update with fused visited-marking ----
        m.x = upd(m.x, R.x, p0 + 0, j);
        m.y = upd(m.y, R.y, p0 + 1, j);
        m.z = upd(m.z, R.z, p0 + 2, j);
        m.w = upd(m.w, R.w, p0 + 3, j);
    }
    if (tid == 0) g_partial[b] = total;
}

// ---------------------------------------------------------------------------
// Kernel 4: final scalar.
// ---------------------------------------------------------------------------
__global__ void final_kernel(float* __restrict__ out) {
    const int t = threadIdx.x;           // 128 threads
    const int lane = t & 31, wid = t >> 5;
    __shared__ float s[4];
    float v = g_partial[t];
    #pragma unroll
    for (int o = 16; o; o >>= 1) v += __shfl_down_sync(0xffffffffu, v, o);
    if (lane == 0) s[wid] = v;
    __syncthreads();
    if (t == 0) out[0] = (s[0] + s[1] + s[2] + s[3]) / (1023.f * (float)BATCH * 2.f);
}

// ---------------------------------------------------------------------------
extern "C" void kernel_launch(void* const* d_in, const int* in_sizes, int n_in,
                              void* d_out, int out_size) {
    (void)in_sizes; (void)n_in; (void)out_size;
    const float* X = (const float*)d_in[0];
    float* out = (float*)d_out;

    prep_kernel<<<16384, 256>>>(X);            // fused norms + bf16 convert
    dist_kernel<<<dim3(8, 8, BATCH), 256>>>();
    nn_kernel<<<BATCH * NPTS / 256, 256>>>();  // top-3 static NNs per point
    prim_kernel<<<BATCH, 256>>>();
    final_kernel<<<1, 128>>>(out);
}